// round 14
// baseline (speedup 1.0000x reference)
#include <cuda_runtime.h>

#define NN  4096
#define ST1 42   // lvl1 array col stride

// 32x64 output tile. lvl1 arrays 24 rows x 42 (stored row = logical+4;
// LH/HL stored col = logical+4, HH stored col = logical+5).
// DEFERRED SCALING: stored subband values omit the Haar 0.5 factors.
//  lvl1 stored = 2*true, lvl2 stored = 4*true, lvl3 stored = 8*true.
//  Biases pre-scaled in pack (b7*2, b5*4, b3*8). idwt3 applies 0.25, idwt2
//  applies 0.25, final idwt1 applies 0.25 (replacing the old 0.5s).
#define O_LH1  0        // 24x42 = 1008
#define O_HL1  1008
#define O_HH1  2016
#define O_LL2  3024     // 12x20
#define O_LH2  3264
#define O_HL2  3504
#define O_HH2  3744
#define O_LL3  3984     // 6x10
#define O_LH3  4044
#define O_HL3  4104
#define O_HH3  4164
#define O_CHH2 4224     // 8x16
#define O_CHH1 4352     // 16x32
#define O_REC2 4864     // 8x16
#define SMEM_FLOATS 4992

__constant__ float2 c_w2[82];

#define CW_F   ((const float*)c_w2)
#define CB7    CW_F[148]
#define CB5    CW_F[149]
#define CB3    CW_F[150]
#define W3S(i) CW_F[152 + (i)]

typedef unsigned long long ull;

__device__ __forceinline__ ull pk2(float lo, float hi) {
    ull r; asm("mov.b64 %0, {%1,%2};" : "=l"(r) : "f"(lo), "f"(hi)); return r;
}
__device__ __forceinline__ void upk2(ull v, float& lo, float& hi) {
    asm("mov.b64 {%0,%1}, %2;" : "=f"(lo), "=f"(hi) : "l"(v));
}
__device__ __forceinline__ ull fma2(ull a, ull b, ull c) {
    ull d; asm("fma.rn.f32x2 %0, %1, %2, %3;" : "=l"(d) : "l"(a), "l"(b), "l"(c));
    return d;
}
__device__ __forceinline__ ull w7p(int i) {
    return reinterpret_cast<const ull*>(c_w2)[i];
}
__device__ __forceinline__ ull w5p(int i) {
    return reinterpret_cast<const ull*>(c_w2)[49 + i];
}

__global__ void pack_weights(float* __restrict__ dst,
                             const float* __restrict__ w3, const float* __restrict__ b3,
                             const float* __restrict__ w5, const float* __restrict__ b5,
                             const float* __restrict__ w7, const float* __restrict__ b7)
{
    int t = threadIdx.x;
    float v = 0.f;
    if (t < 98)        v = w7[t >> 1];
    else if (t < 148)  v = w5[(t - 98) >> 1];
    else if (t == 148) v = b7[0] * 2.0f;   // deferred-scaling bias pre-scale
    else if (t == 149) v = b5[0] * 4.0f;
    else if (t == 150) v = b3[0] * 8.0f;
    else if (t >= 152 && t < 161) v = w3[t - 152];
    if (t < 164) dst[t] = v;
}

__global__ __launch_bounds__(256, 8) void fused_wavelet_kernel(
    const float* __restrict__ x, float* __restrict__ out)
{
    __shared__ float s[SMEM_FLOATS];
    const int tid = threadIdx.x;
    const int bx = blockIdx.x, by = blockIdx.y;

    // ---- S1: fused level-1 + level-2 DWT, unscaled butterflies. ----
    if (tid < 240) {
        int ap = tid / 20, aq = tid - ap * 20;
        int gr = by * 32 - 8 + 4 * ap;
        int gc = bx * 64 - 8 + 4 * aq;
        float4 A = make_float4(0.f, 0.f, 0.f, 0.f), B = A, C = A, D = A;
        if ((unsigned)gr < NN && (unsigned)gc < NN) {
            const float* p = x + (size_t)gr * NN + gc;
            A = *reinterpret_cast<const float4*>(p);
            B = *reinterpret_cast<const float4*>(p + NN);
            C = *reinterpret_cast<const float4*>(p + 2 * NN);
            D = *reinterpret_cast<const float4*>(p + 3 * NN);
        }
        // quad (row-pair A,B | C,D), explicit CSE, no 0.5 scaling
        float ah0 = A.x + A.y, ad0 = A.x - A.y, ah1 = A.z + A.w, ad1 = A.z - A.w;
        float bh0 = B.x + B.y, bd0 = B.x - B.y, bh1 = B.z + B.w, bd1 = B.z - B.w;
        float ch0 = C.x + C.y, cd0 = C.x - C.y, ch1 = C.z + C.w, cd1 = C.z - C.w;
        float dh0 = D.x + D.y, dd0 = D.x - D.y, dh1 = D.z + D.w, dd1 = D.z - D.w;

        float ll00 = ah0 + bh0, lh00 = ah0 - bh0, hl00 = ad0 + bd0, hh00 = ad0 - bd0;
        float ll01 = ah1 + bh1, lh01 = ah1 - bh1, hl01 = ad1 + bd1, hh01 = ad1 - bd1;
        float ll10 = ch0 + dh0, lh10 = ch0 - dh0, hl10 = cd0 + dd0, hh10 = cd0 - dd0;
        float ll11 = ch1 + dh1, lh11 = ch1 - dh1, hl11 = cd1 + dd1, hh11 = cd1 - dd1;

        int r0 = (2 * ap) * ST1 + 2 * aq;
        int r1 = r0 + ST1;
        *reinterpret_cast<float2*>(&s[O_LH1 + r0]) = make_float2(lh00, lh01);
        *reinterpret_cast<float2*>(&s[O_LH1 + r1]) = make_float2(lh10, lh11);
        *reinterpret_cast<float2*>(&s[O_HL1 + r0]) = make_float2(hl00, hl01);
        *reinterpret_cast<float2*>(&s[O_HL1 + r1]) = make_float2(hl10, hl11);
        s[O_HH1 + r0 + 1] = hh00;
        s[O_HH1 + r0 + 2] = hh01;
        s[O_HH1 + r1 + 1] = hh10;
        s[O_HH1 + r1 + 2] = hh11;

        // lvl2 butterfly (unscaled), explicit CSE
        float su = ll00 + ll01, sw = ll10 + ll11;
        float du = ll00 - ll01, dz = ll10 - ll11;
        s[O_LL2 + tid] = su + sw;
        s[O_LH2 + tid] = su - sw;
        s[O_HL2 + tid] = du + dz;
        s[O_HH2 + tid] = du - dz;
    }
    __syncthreads();

    // ---- S2 (one phase, disjoint warp ranges; lvl3 on warps 6-7 for SMSP balance):
    //  tid 0-63:    conv7 -> CHH1 (16x32), 2 cols x 4 rows, f32x2.  (SMSP 0,1)
    //  tid 64-95:   conv5 -> CHH2 (8x16), 2 cols x 2 rows, f32x2.   (SMSP 2)
    //  tid 192-255: lvl3 DWT (60 pos), bar.sync(1,64), IDWT3+conv3. (SMSP 2,3)
    if (tid < 64) {
        int r = tid >> 4;
        int c = tid & 15;
        float bv = CB7;                       // pre-scaled 2*b7
        ull acc0 = pk2(bv, bv), acc1 = acc0, acc2 = acc0, acc3 = acc0;
#pragma unroll
        for (int u = 0; u < 10; u++) {
            const ull* rowq = reinterpret_cast<const ull*>(
                &s[O_HH1 + (4 * r + 1 + u) * ST1 + 2 * c + 2]);
            ull e0 = rowq[0], e1 = rowq[1], e2 = rowq[2], e3 = rowq[3];
            float a1x, a1y, a3x, a3y, a5x, a5y, dump0, dump1;
            upk2(e0, dump0, a1x);
            upk2(e1, a1y, a3x);
            upk2(e2, a3y, a5x);
            upk2(e3, a5y, dump1);
            ull xp[7];
            xp[0] = e0;
            xp[1] = pk2(a1x, a1y);
            xp[2] = e1;
            xp[3] = pk2(a3x, a3y);
            xp[4] = e2;
            xp[5] = pk2(a5x, a5y);
            xp[6] = e3;
#pragma unroll
            for (int k = 0; k < 4; k++) {
                int uu = u - k;
                if (uu >= 0 && uu < 7) {
                    ull a = (k == 0) ? acc0 : (k == 1) ? acc1 : (k == 2) ? acc2 : acc3;
#pragma unroll
                    for (int v = 0; v < 7; v++) a = fma2(xp[v], w7p(uu * 7 + v), a);
                    if (k == 0) acc0 = a; else if (k == 1) acc1 = a;
                    else if (k == 2) acc2 = a; else acc3 = a;
                }
            }
        }
        float lo, hi;
        upk2(acc0, lo, hi);
        *reinterpret_cast<float2*>(&s[O_CHH1 + (4 * r + 0) * 32 + 2 * c]) = make_float2(lo, hi);
        upk2(acc1, lo, hi);
        *reinterpret_cast<float2*>(&s[O_CHH1 + (4 * r + 1) * 32 + 2 * c]) = make_float2(lo, hi);
        upk2(acc2, lo, hi);
        *reinterpret_cast<float2*>(&s[O_CHH1 + (4 * r + 2) * 32 + 2 * c]) = make_float2(lo, hi);
        upk2(acc3, lo, hi);
        *reinterpret_cast<float2*>(&s[O_CHH1 + (4 * r + 3) * 32 + 2 * c]) = make_float2(lo, hi);
    } else if (tid < 96) {
        int t2 = tid - 64;
        int r = t2 >> 3;
        int c = t2 & 7;
        float bv = CB5;                       // pre-scaled 4*b5
        ull acc0 = pk2(bv, bv), acc1 = acc0;
#pragma unroll
        for (int u = 0; u < 6; u++) {
            const ull* rowq = reinterpret_cast<const ull*>(
                &s[O_HH2 + (2 * r + u) * 20 + 2 * c]);
            ull e0 = rowq[0], e1 = rowq[1], e2 = rowq[2];
            float a1x, a1y, a3x, a3y, dump0, dump1;
            upk2(e0, dump0, a1x);
            upk2(e1, a1y, a3x);
            upk2(e2, a3y, dump1);
            ull xp[5];
            xp[0] = e0;
            xp[1] = pk2(a1x, a1y);
            xp[2] = e1;
            xp[3] = pk2(a3x, a3y);
            xp[4] = e2;
            if (u < 5) {
#pragma unroll
                for (int v = 0; v < 5; v++) acc0 = fma2(xp[v], w5p(u * 5 + v), acc0);
            }
            if (u >= 1) {
#pragma unroll
                for (int v = 0; v < 5; v++) acc1 = fma2(xp[v], w5p((u - 1) * 5 + v), acc1);
            }
        }
        float lo, hi;
        upk2(acc0, lo, hi);
        *reinterpret_cast<float2*>(&s[O_CHH2 + (2 * r) * 16 + 2 * c]) = make_float2(lo, hi);
        upk2(acc1, lo, hi);
        *reinterpret_cast<float2*>(&s[O_CHH2 + (2 * r + 1) * 16 + 2 * c]) = make_float2(lo, hi);
    } else if (tid >= 192) {
        int t3 = tid - 192;
        if (t3 < 60) {
            int as = t3 / 10, at = t3 - as * 10;
            float2 t0 = *reinterpret_cast<const float2*>(&s[O_LL2 + (2 * as) * 20 + 2 * at]);
            float2 t1 = *reinterpret_cast<const float2*>(&s[O_LL2 + (2 * as + 1) * 20 + 2 * at]);
            float su = t0.x + t0.y, sw = t1.x + t1.y;
            float du = t0.x - t0.y, dz = t1.x - t1.y;
            s[O_LL3 + t3] = su + sw;          // unscaled (8*true)
            s[O_LH3 + t3] = su - sw;
            s[O_HL3 + t3] = du + dz;
            s[O_HH3 + t3] = du - dz;
        }
        asm volatile("bar.sync 1, 64;" ::: "memory");
        if (t3 < 32) {
            int i = t3 >> 3, j = t3 & 7;
            float d = CB3;                    // pre-scaled 8*b3
#pragma unroll
            for (int u = 0; u < 3; u++)
#pragma unroll
                for (int v = 0; v < 3; v++)
                    d += s[O_HH3 + (i + u) * 10 + (j + v)] * W3S(u * 3 + v);
            float a = s[O_LL3 + (i + 1) * 10 + (j + 1)];
            float b = s[O_LH3 + (i + 1) * 10 + (j + 1)];
            float c = s[O_HL3 + (i + 1) * 10 + (j + 1)];
            // idwt3 with 0.25: stored REC2 lands at lvl2 scale (4*true)
            *reinterpret_cast<float2*>(&s[O_REC2 + (2 * i) * 16 + 2 * j]) =
                make_float2((a + b + c + d) * 0.25f, (a + b - c - d) * 0.25f);
            *reinterpret_cast<float2*>(&s[O_REC2 + (2 * i + 1) * 16 + 2 * j]) =
                make_float2((a - b + c - d) * 0.25f, (a - b - c + d) * 0.25f);
        }
    }
    __syncthreads();

    // ---- S3: fused IDWT2 + IDWT1 -> global. 256 threads. ----
    {
        int i = tid >> 4;
        int q = tid & 15;
        int p = i >> 1, k = i & 1;
        float a2 = s[O_REC2 + p * 16 + q];
        float b2 = s[O_LH2 + (p + 2) * 20 + (q + 2)];
        float c2 = s[O_HL2 + (p + 2) * 20 + (q + 2)];
        float d2 = s[O_CHH2 + p * 16 + q];
        float ra, rb;
        if (k == 0) {
            ra = (a2 + b2 + c2 + d2) * 0.25f;   // rec1 at lvl1 scale (2*true)
            rb = (a2 + b2 - c2 - d2) * 0.25f;
        } else {
            ra = (a2 - b2 + c2 - d2) * 0.25f;
            rb = (a2 - b2 - c2 + d2) * 0.25f;
        }
        float2 b = *reinterpret_cast<const float2*>(&s[O_LH1 + (i + 4) * ST1 + 2 * q + 4]);
        float2 c = *reinterpret_cast<const float2*>(&s[O_HL1 + (i + 4) * ST1 + 2 * q + 4]);
        float2 d = *reinterpret_cast<const float2*>(&s[O_CHH1 + i * 32 + 2 * q]);
        float4 e0, e1;
        e0.x = (ra + b.x + c.x + d.x) * 0.25f;  // final: 0.25 absorbs both scales
        e0.y = (ra + b.x - c.x - d.x) * 0.25f;
        e0.z = (rb + b.y + c.y + d.y) * 0.25f;
        e0.w = (rb + b.y - c.y - d.y) * 0.25f;
        e1.x = (ra - b.x + c.x - d.x) * 0.25f;
        e1.y = (ra - b.x - c.x + d.x) * 0.25f;
        e1.z = (rb - b.y + c.y - d.y) * 0.25f;
        e1.w = (rb - b.y - c.y + d.y) * 0.25f;
        int gr = by * 32 + 2 * i;
        int gc = bx * 64 + 4 * q;
        *reinterpret_cast<float4*>(out + (size_t)gr * NN + gc)       = e0;
        *reinterpret_cast<float4*>(out + (size_t)(gr + 1) * NN + gc) = e1;
    }
}

extern "C" void kernel_launch(void* const* d_in, const int* in_sizes, int n_in,
                              void* d_out, int out_size)
{
    const float* x = (const float*)d_in[0];
    float* out = (float*)d_out;

    void* caddr = nullptr;
    cudaGetSymbolAddress(&caddr, c_w2);
    pack_weights<<<1, 192>>>((float*)caddr,
                             (const float*)d_in[1], (const float*)d_in[2],
                             (const float*)d_in[3], (const float*)d_in[4],
                             (const float*)d_in[5], (const float*)d_in[6]);

    dim3 grid(NN / 64, NN / 32);
    fused_wavelet_kernel<<<grid, 256>>>(x, out);
}

// round 15
// speedup vs baseline: 1.0454x; 1.0454x over previous
#include <cuda_runtime.h>

#define NN  4096
#define ST1 42   // lvl1 array col stride

// 32x64 output tile. lvl1 arrays 24 rows x 42 (stored row = logical+4;
// LH/HL stored col = logical+4, HH stored col = logical+5).
// DEFERRED SCALING: lvl1 stored = 2*true, lvl2 = 4*true, lvl3 = 8*true.
// Biases pre-scaled in pack (b7*2, b5*4, b3*8); idwt3/idwt2/idwt1 use 0.25.
#define O_LH1  0        // 24x42 = 1008
#define O_HL1  1008
#define O_HH1  2016
#define O_LL2  3024     // 12x20
#define O_LH2  3264
#define O_HL2  3504
#define O_HH2  3744
#define O_LL3  3984     // 6x10
#define O_LH3  4044
#define O_HL3  4104
#define O_HH3  4164
#define O_CHH2 4224     // 8x16
#define O_CHH1 4352     // 16x32
#define O_REC2 4864     // 8x16
#define SMEM_FLOATS 4992

__constant__ float2 c_w2[82];

#define CW_F   ((const float*)c_w2)
#define CB7    CW_F[148]
#define CB5    CW_F[149]
#define CB3    CW_F[150]
#define W3S(i) CW_F[152 + (i)]

typedef unsigned long long ull;

__device__ __forceinline__ ull pk2(float lo, float hi) {
    ull r; asm("mov.b64 %0, {%1,%2};" : "=l"(r) : "f"(lo), "f"(hi)); return r;
}
__device__ __forceinline__ void upk2(ull v, float& lo, float& hi) {
    asm("mov.b64 {%0,%1}, %2;" : "=f"(lo), "=f"(hi) : "l"(v));
}
__device__ __forceinline__ ull fma2(ull a, ull b, ull c) {
    ull d; asm("fma.rn.f32x2 %0, %1, %2, %3;" : "=l"(d) : "l"(a), "l"(b), "l"(c));
    return d;
}
__device__ __forceinline__ ull w7p(int i) {
    return reinterpret_cast<const ull*>(c_w2)[i];
}
__device__ __forceinline__ ull w5p(int i) {
    return reinterpret_cast<const ull*>(c_w2)[49 + i];
}

__global__ void pack_weights(float* __restrict__ dst,
                             const float* __restrict__ w3, const float* __restrict__ b3,
                             const float* __restrict__ w5, const float* __restrict__ b5,
                             const float* __restrict__ w7, const float* __restrict__ b7)
{
    int t = threadIdx.x;
    float v = 0.f;
    if (t < 98)        v = w7[t >> 1];
    else if (t < 148)  v = w5[(t - 98) >> 1];
    else if (t == 148) v = b7[0] * 2.0f;
    else if (t == 149) v = b5[0] * 4.0f;
    else if (t == 150) v = b3[0] * 8.0f;
    else if (t >= 152 && t < 161) v = w3[t - 152];
    if (t < 164) dst[t] = v;
}

__global__ __launch_bounds__(256, 8) void fused_wavelet_kernel(
    const float* __restrict__ x, float* __restrict__ out)
{
    __shared__ float s[SMEM_FLOATS];
    const int tid = threadIdx.x;
    const int bx = blockIdx.x, by = blockIdx.y;

    // ---- S1: fused level-1 + level-2 DWT, unscaled CSE butterflies. ----
    if (tid < 240) {
        int ap = tid / 20, aq = tid - ap * 20;
        int gr = by * 32 - 8 + 4 * ap;
        int gc = bx * 64 - 8 + 4 * aq;
        float4 A = make_float4(0.f, 0.f, 0.f, 0.f), B = A, C = A, D = A;
        if ((unsigned)gr < NN && (unsigned)gc < NN) {
            const float* p = x + (size_t)gr * NN + gc;
            A = *reinterpret_cast<const float4*>(p);
            B = *reinterpret_cast<const float4*>(p + NN);
            C = *reinterpret_cast<const float4*>(p + 2 * NN);
            D = *reinterpret_cast<const float4*>(p + 3 * NN);
        }
        float ah0 = A.x + A.y, ad0 = A.x - A.y, ah1 = A.z + A.w, ad1 = A.z - A.w;
        float bh0 = B.x + B.y, bd0 = B.x - B.y, bh1 = B.z + B.w, bd1 = B.z - B.w;
        float ch0 = C.x + C.y, cd0 = C.x - C.y, ch1 = C.z + C.w, cd1 = C.z - C.w;
        float dh0 = D.x + D.y, dd0 = D.x - D.y, dh1 = D.z + D.w, dd1 = D.z - D.w;

        float ll00 = ah0 + bh0, lh00 = ah0 - bh0, hl00 = ad0 + bd0, hh00 = ad0 - bd0;
        float ll01 = ah1 + bh1, lh01 = ah1 - bh1, hl01 = ad1 + bd1, hh01 = ad1 - bd1;
        float ll10 = ch0 + dh0, lh10 = ch0 - dh0, hl10 = cd0 + dd0, hh10 = cd0 - dd0;
        float ll11 = ch1 + dh1, lh11 = ch1 - dh1, hl11 = cd1 + dd1, hh11 = cd1 - dd1;

        int r0 = (2 * ap) * ST1 + 2 * aq;
        int r1 = r0 + ST1;
        *reinterpret_cast<float2*>(&s[O_LH1 + r0]) = make_float2(lh00, lh01);
        *reinterpret_cast<float2*>(&s[O_LH1 + r1]) = make_float2(lh10, lh11);
        *reinterpret_cast<float2*>(&s[O_HL1 + r0]) = make_float2(hl00, hl01);
        *reinterpret_cast<float2*>(&s[O_HL1 + r1]) = make_float2(hl10, hl11);
        s[O_HH1 + r0 + 1] = hh00;
        s[O_HH1 + r0 + 2] = hh01;
        s[O_HH1 + r1 + 1] = hh10;
        s[O_HH1 + r1 + 2] = hh11;

        float su = ll00 + ll01, sw = ll10 + ll11;
        float du = ll00 - ll01, dz = ll10 - ll11;
        s[O_LL2 + tid] = su + sw;
        s[O_LH2 + tid] = su - sw;
        s[O_HL2 + tid] = du + dz;
        s[O_HH2 + tid] = du - dz;
    }
    __syncthreads();

    // ---- S2 (R13 warp layout):
    //  tid 0-63:   conv7 -> CHH1 (16x32), 2 cols x 4 rows, f32x2.  (warps 0,1)
    //  tid 64-95:  conv5 -> CHH2 (8x16), 2 cols x 2 rows, f32x2.   (warp 2)
    //  tid 96-159: lvl3 DWT (60 pos), bar.sync(1,64), IDWT3+conv3. (warps 3,4)
    if (tid < 64) {
        int r = tid >> 4;
        int c = tid & 15;
        float bv = CB7;                       // pre-scaled 2*b7
        ull acc0 = pk2(bv, bv), acc1 = acc0, acc2 = acc0, acc3 = acc0;
#pragma unroll
        for (int u = 0; u < 10; u++) {
            const ull* rowq = reinterpret_cast<const ull*>(
                &s[O_HH1 + (4 * r + 1 + u) * ST1 + 2 * c + 2]);
            ull e0 = rowq[0], e1 = rowq[1], e2 = rowq[2], e3 = rowq[3];
            float a1x, a1y, a3x, a3y, a5x, a5y, dump0, dump1;
            upk2(e0, dump0, a1x);
            upk2(e1, a1y, a3x);
            upk2(e2, a3y, a5x);
            upk2(e3, a5y, dump1);
            ull xp[7];
            xp[0] = e0;
            xp[1] = pk2(a1x, a1y);
            xp[2] = e1;
            xp[3] = pk2(a3x, a3y);
            xp[4] = e2;
            xp[5] = pk2(a5x, a5y);
            xp[6] = e3;
#pragma unroll
            for (int k = 0; k < 4; k++) {
                int uu = u - k;
                if (uu >= 0 && uu < 7) {
                    ull a = (k == 0) ? acc0 : (k == 1) ? acc1 : (k == 2) ? acc2 : acc3;
#pragma unroll
                    for (int v = 0; v < 7; v++) a = fma2(xp[v], w7p(uu * 7 + v), a);
                    if (k == 0) acc0 = a; else if (k == 1) acc1 = a;
                    else if (k == 2) acc2 = a; else acc3 = a;
                }
            }
        }
        float lo, hi;
        upk2(acc0, lo, hi);
        *reinterpret_cast<float2*>(&s[O_CHH1 + (4 * r + 0) * 32 + 2 * c]) = make_float2(lo, hi);
        upk2(acc1, lo, hi);
        *reinterpret_cast<float2*>(&s[O_CHH1 + (4 * r + 1) * 32 + 2 * c]) = make_float2(lo, hi);
        upk2(acc2, lo, hi);
        *reinterpret_cast<float2*>(&s[O_CHH1 + (4 * r + 2) * 32 + 2 * c]) = make_float2(lo, hi);
        upk2(acc3, lo, hi);
        *reinterpret_cast<float2*>(&s[O_CHH1 + (4 * r + 3) * 32 + 2 * c]) = make_float2(lo, hi);
    } else if (tid < 96) {
        int t2 = tid - 64;
        int r = t2 >> 3;
        int c = t2 & 7;
        float bv = CB5;                       // pre-scaled 4*b5
        ull acc0 = pk2(bv, bv), acc1 = acc0;
#pragma unroll
        for (int u = 0; u < 6; u++) {
            const ull* rowq = reinterpret_cast<const ull*>(
                &s[O_HH2 + (2 * r + u) * 20 + 2 * c]);
            ull e0 = rowq[0], e1 = rowq[1], e2 = rowq[2];
            float a1x, a1y, a3x, a3y, dump0, dump1;
            upk2(e0, dump0, a1x);
            upk2(e1, a1y, a3x);
            upk2(e2, a3y, dump1);
            ull xp[5];
            xp[0] = e0;
            xp[1] = pk2(a1x, a1y);
            xp[2] = e1;
            xp[3] = pk2(a3x, a3y);
            xp[4] = e2;
            if (u < 5) {
#pragma unroll
                for (int v = 0; v < 5; v++) acc0 = fma2(xp[v], w5p(u * 5 + v), acc0);
            }
            if (u >= 1) {
#pragma unroll
                for (int v = 0; v < 5; v++) acc1 = fma2(xp[v], w5p((u - 1) * 5 + v), acc1);
            }
        }
        float lo, hi;
        upk2(acc0, lo, hi);
        *reinterpret_cast<float2*>(&s[O_CHH2 + (2 * r) * 16 + 2 * c]) = make_float2(lo, hi);
        upk2(acc1, lo, hi);
        *reinterpret_cast<float2*>(&s[O_CHH2 + (2 * r + 1) * 16 + 2 * c]) = make_float2(lo, hi);
    } else if (tid < 160) {
        int t3 = tid - 96;
        if (t3 < 60) {
            int as = t3 / 10, at = t3 - as * 10;
            float2 t0 = *reinterpret_cast<const float2*>(&s[O_LL2 + (2 * as) * 20 + 2 * at]);
            float2 t1 = *reinterpret_cast<const float2*>(&s[O_LL2 + (2 * as + 1) * 20 + 2 * at]);
            float su = t0.x + t0.y, sw = t1.x + t1.y;
            float du = t0.x - t0.y, dz = t1.x - t1.y;
            s[O_LL3 + t3] = su + sw;          // unscaled (8*true)
            s[O_LH3 + t3] = su - sw;
            s[O_HL3 + t3] = du + dz;
            s[O_HH3 + t3] = du - dz;
        }
        asm volatile("bar.sync 1, 64;" ::: "memory");
        if (t3 < 32) {
            int i = t3 >> 3, j = t3 & 7;
            float d = CB3;                    // pre-scaled 8*b3
#pragma unroll
            for (int u = 0; u < 3; u++)
#pragma unroll
                for (int v = 0; v < 3; v++)
                    d += s[O_HH3 + (i + u) * 10 + (j + v)] * W3S(u * 3 + v);
            float a = s[O_LL3 + (i + 1) * 10 + (j + 1)];
            float b = s[O_LH3 + (i + 1) * 10 + (j + 1)];
            float c = s[O_HL3 + (i + 1) * 10 + (j + 1)];
            // idwt3 with 0.25: REC2 lands at lvl2 scale (4*true)
            *reinterpret_cast<float2*>(&s[O_REC2 + (2 * i) * 16 + 2 * j]) =
                make_float2((a + b + c + d) * 0.25f, (a + b - c - d) * 0.25f);
            *reinterpret_cast<float2*>(&s[O_REC2 + (2 * i + 1) * 16 + 2 * j]) =
                make_float2((a - b + c - d) * 0.25f, (a - b - c + d) * 0.25f);
        }
    }
    __syncthreads();

    // ---- S3: fused IDWT2 + IDWT1 -> global. 256 threads. ----
    {
        int i = tid >> 4;
        int q = tid & 15;
        int p = i >> 1, k = i & 1;
        float a2 = s[O_REC2 + p * 16 + q];
        float b2 = s[O_LH2 + (p + 2) * 20 + (q + 2)];
        float c2 = s[O_HL2 + (p + 2) * 20 + (q + 2)];
        float d2 = s[O_CHH2 + p * 16 + q];
        float ra, rb;
        if (k == 0) {
            ra = (a2 + b2 + c2 + d2) * 0.25f;   // rec1 at lvl1 scale (2*true)
            rb = (a2 + b2 - c2 - d2) * 0.25f;
        } else {
            ra = (a2 - b2 + c2 - d2) * 0.25f;
            rb = (a2 - b2 - c2 + d2) * 0.25f;
        }
        float2 b = *reinterpret_cast<const float2*>(&s[O_LH1 + (i + 4) * ST1 + 2 * q + 4]);
        float2 c = *reinterpret_cast<const float2*>(&s[O_HL1 + (i + 4) * ST1 + 2 * q + 4]);
        float2 d = *reinterpret_cast<const float2*>(&s[O_CHH1 + i * 32 + 2 * q]);
        float4 e0, e1;
        e0.x = (ra + b.x + c.x + d.x) * 0.25f;
        e0.y = (ra + b.x - c.x - d.x) * 0.25f;
        e0.z = (rb + b.y + c.y + d.y) * 0.25f;
        e0.w = (rb + b.y - c.y - d.y) * 0.25f;
        e1.x = (ra - b.x + c.x - d.x) * 0.25f;
        e1.y = (ra - b.x - c.x + d.x) * 0.25f;
        e1.z = (rb - b.y + c.y - d.y) * 0.25f;
        e1.w = (rb - b.y - c.y + d.y) * 0.25f;
        int gr = by * 32 + 2 * i;
        int gc = bx * 64 + 4 * q;
        *reinterpret_cast<float4*>(out + (size_t)gr * NN + gc)       = e0;
        *reinterpret_cast<float4*>(out + (size_t)(gr + 1) * NN + gc) = e1;
    }
}

extern "C" void kernel_launch(void* const* d_in, const int* in_sizes, int n_in,
                              void* d_out, int out_size)
{
    const float* x = (const float*)d_in[0];
    float* out = (float*)d_out;

    void* caddr = nullptr;
    cudaGetSymbolAddress(&caddr, c_w2);
    pack_weights<<<1, 192>>>((float*)caddr,
                             (const float*)d_in[1], (const float*)d_in[2],
                             (const float*)d_in[3], (const float*)d_in[4],
                             (const float*)d_in[5], (const float*)d_in[6]);

    dim3 grid(NN / 64, NN / 32);
    fused_wavelet_kernel<<<grid, 256>>>(x, out);
}